// round 5
// baseline (speedup 1.0000x reference)
#include <cuda_runtime.h>
#include <cstdint>

#define NR 13824
#define ND 1728
#define FDIM 512      // feature layout: [0,256) repr | [256,384) con | [384,512) off
#define OUTC 64
#define QROWS 32

#define SM_SCALE 0.25f                       // 1/(sqrt(256)*0.25)
#define INV_SQRT_H 0.088388347648318447f     // 1/sqrt(128)
#define MAX_CONTRAST 1.8f

typedef unsigned long long u64;

// ---- packed f32x2 helpers (sm_100a) ---------------------------------------
__device__ __forceinline__ u64 pack2(float lo, float hi) {
    u64 r; asm("mov.b64 %0, {%1, %2};" : "=l"(r) : "f"(lo), "f"(hi)); return r;
}
__device__ __forceinline__ u64 ffma2(u64 a, u64 b, u64 c) {
    u64 d; asm("fma.rn.f32x2 %0, %1, %2, %3;" : "=l"(d) : "l"(a), "l"(b), "l"(c));
    return d;
}
__device__ __forceinline__ u64 fmul2(u64 a, u64 b) {
    u64 d; asm("mul.rn.f32x2 %0, %1, %2;" : "=l"(d) : "l"(a), "l"(b)); return d;
}
__device__ __forceinline__ float2 unpack2(u64 v) {
    float lo, hi; asm("mov.b64 {%0, %1}, %2;" : "=f"(lo), "=f"(hi) : "l"(v));
    return make_float2(lo, hi);
}
__device__ __forceinline__ float tanh_hw(float x) {
    float y; asm("tanh.approx.f32 %0, %1;" : "=f"(y) : "f"(x)); return y;
}

// Scratch (static __device__ arrays: allocation-guard safe)
__device__ float g_rfeat[(size_t)NR * FDIM];
__device__ float g_dfeat[(size_t)ND * FDIM];

// ---------------------------------------------------------------------------
// Merged projection GEMM, double-buffered.
// grid = (8, rows/64); blockIdx.x selects which W (proj/con/off) by column.
// out[m, n0 + n] = sum_k (L+P)[m,k] * W[k,n] + bias[n]
// ---------------------------------------------------------------------------
__global__ __launch_bounds__(256) void proj_kernel(
    const float* __restrict__ L, const float* __restrict__ P,
    const float* __restrict__ Wp, const float* __restrict__ bp,
    const float* __restrict__ Wc, const float* __restrict__ bc,
    const float* __restrict__ Wo, const float* __restrict__ bo,
    int which)
{
    __shared__ float As[2][16][68];   // [buf][k][m-row]
    __shared__ float Bs[2][16][64];   // [buf][k][n-col]
    float* out = which ? g_dfeat : g_rfeat;

    const int tid = threadIdx.x;
    const int tx = tid & 15, ty = tid >> 4;
    const int m0 = blockIdx.y * 64;
    const int n0 = blockIdx.x * 64;

    const float* W; const float* bias; int N, nloc;
    if (n0 < 256)      { W = Wp; bias = bp; N = 256; nloc = n0; }
    else if (n0 < 384) { W = Wc; bias = bc; N = 128; nloc = n0 - 256; }
    else               { W = Wo; bias = bo; N = 128; nloc = n0 - 384; }

    const int arow = tid & 63;        // A row (0..63)
    const int akq  = (tid >> 6) * 4;  // A k-quad (0,4,8,12)
    const int bcol = tid & 63;        // B col
    const int bk   = tid >> 6;        // B k base (0..3)

    float4 a_st; float b_st[4];

    auto load_chunk = [&](int k0) {
        float4 l4 = *(const float4*)&L[(size_t)(m0 + arow) * FDIM + k0 + akq];
        float4 p4 = *(const float4*)&P[(size_t)(m0 + arow) * FDIM + k0 + akq];
        a_st = make_float4(l4.x + p4.x, l4.y + p4.y, l4.z + p4.z, l4.w + p4.w);
#pragma unroll
        for (int j = 0; j < 4; j++)
            b_st[j] = W[(size_t)(k0 + bk + 4 * j) * N + nloc + bcol];
    };
    auto store_chunk = [&](int pp) {
        As[pp][akq + 0][arow] = a_st.x;
        As[pp][akq + 1][arow] = a_st.y;
        As[pp][akq + 2][arow] = a_st.z;
        As[pp][akq + 3][arow] = a_st.w;
#pragma unroll
        for (int j = 0; j < 4; j++)
            Bs[pp][bk + 4 * j][bcol] = b_st[j];
    };

    u64 acc[4][2] = {};

    load_chunk(0);
    store_chunk(0);
    load_chunk(16);
    __syncthreads();
    int p = 0;
    for (int ck = 0; ck < 32; ck++) {
#pragma unroll
        for (int kk = 0; kk < 16; kk++) {
            float4 a4 = *(const float4*)&As[p][kk][4 * ty];
            ulonglong2 b2 = *(const ulonglong2*)&Bs[p][kk][4 * tx];
            float av[4] = {a4.x, a4.y, a4.z, a4.w};
#pragma unroll
            for (int i = 0; i < 4; i++) {
                u64 ap = pack2(av[i], av[i]);
                acc[i][0] = ffma2(ap, b2.x, acc[i][0]);
                acc[i][1] = ffma2(ap, b2.y, acc[i][1]);
            }
        }
        if (ck + 1 < 32) store_chunk(p ^ 1);
        if (ck + 2 < 32) load_chunk((ck + 2) * 16);
        __syncthreads();
        p ^= 1;
    }

    float4 bia = *(const float4*)&bias[nloc + 4 * tx];
#pragma unroll
    for (int i = 0; i < 4; i++) {
        float2 v0 = unpack2(acc[i][0]);
        float2 v1 = unpack2(acc[i][1]);
        float4 o4 = make_float4(v0.x + bia.x, v0.y + bia.y,
                                v1.x + bia.z, v1.y + bia.w);
        *(float4*)&out[(size_t)(m0 + 4 * ty + i) * FDIM + n0 + 4 * tx] = o4;
    }
}

// ---------------------------------------------------------------------------
// Fused attention, double-buffered. 32 Q rows per CTA, grid = NR/32 = 432.
// ---------------------------------------------------------------------------
__global__ __launch_bounds__(256, 3) void attn_kernel(
    const float* __restrict__ Vmat,   // pooled_domains [ND][64]
    float* __restrict__ out)          // [NR][64]
{
    __shared__ float Qs[2][16][36];   // [buf][k][q-row]
    __shared__ float Ks[2][16][68];   // [buf][k][d-row]
    __shared__ float PCT[64][36];     // p*contrast, TRANSPOSED [d-col][q-row]
    __shared__ float Vs[64][64];

    const int tid = threadIdx.x;
    const int tx = tid & 15, ty = tid >> 4;   // frag: rows {2ty,2ty+1} x cols 4tx..4tx+3
    const int r0 = blockIdx.x * QROWS;
    const float* Qbase = g_rfeat + (size_t)r0 * FDIM;

    const int qrow = tid & 31;         // Q row
    const int qk   = (tid >> 5) * 2;   // Q k-pair
    const int krow = tid >> 2;         // K row (0..63)
    const int kk4  = (tid & 3) * 4;    // K k-quad

    float2 qst; float4 kst;

    u64 acc[2][2] = {};
    float m_i[2] = {-3.0e38f, -3.0e38f};
    float l_part[2] = {}, off_part[2] = {};

    for (int d0 = 0; d0 < ND; d0 += 64) {
        const float* Kbase = g_dfeat + (size_t)d0 * FDIM;

        auto load_chunk = [&](int k0) {
            qst = *(const float2*)&Qbase[(size_t)qrow * FDIM + k0 + qk];
            kst = *(const float4*)&Kbase[(size_t)krow * FDIM + k0 + kk4];
        };
        auto store_chunk = [&](int pp) {
            Qs[pp][qk + 0][qrow] = qst.x;
            Qs[pp][qk + 1][qrow] = qst.y;
            Ks[pp][kk4 + 0][krow] = kst.x;
            Ks[pp][kk4 + 1][krow] = kst.y;
            Ks[pp][kk4 + 2][krow] = kst.z;
            Ks[pp][kk4 + 3][krow] = kst.w;
        };
        auto compute = [&](int pp, u64 (&s)[2][2]) {
#pragma unroll
            for (int kk = 0; kk < 16; kk++) {
                float2 a2 = *(const float2*)&Qs[pp][kk][2 * ty];
                ulonglong2 b2 = *(const ulonglong2*)&Ks[pp][kk][4 * tx];
                u64 a0 = pack2(a2.x, a2.x);
                u64 a1 = pack2(a2.y, a2.y);
                s[0][0] = ffma2(a0, b2.x, s[0][0]);
                s[0][1] = ffma2(a0, b2.y, s[0][1]);
                s[1][0] = ffma2(a1, b2.x, s[1][0]);
                s[1][1] = ffma2(a1, b2.y, s[1][1]);
            }
        };

        u64 s_repr[2][2] = {};
        u64 s_con[2][2]  = {};
        u64 s_off[2][2]  = {};

        load_chunk(0);
        store_chunk(0);
        load_chunk(16);
        __syncthreads();
        int p = 0;
        for (int ck = 0; ck < 32; ck++) {
            if (ck < 16)      compute(p, s_repr);
            else if (ck < 24) compute(p, s_con);
            else              compute(p, s_off);
            if (ck + 1 < 32) store_chunk(p ^ 1);
            if (ck + 2 < 32) load_chunk((ck + 2) * 16);
            __syncthreads();
            p ^= 1;
        }

        // ---- per-tile softmax epilogue (registers only) ----
        float alpha[2], pc[2][4];
#pragma unroll
        for (int i = 0; i < 2; i++) {
            float2 rA = unpack2(s_repr[i][0]);
            float2 rB = unpack2(s_repr[i][1]);
            float lg[4] = {rA.x * SM_SCALE, rA.y * SM_SCALE,
                           rB.x * SM_SCALE, rB.y * SM_SCALE};
            float mx = fmaxf(fmaxf(lg[0], lg[1]), fmaxf(lg[2], lg[3]));
#pragma unroll
            for (int d = 1; d < 16; d <<= 1)
                mx = fmaxf(mx, __shfl_xor_sync(0xffffffffu, mx, d));
            float m_new = fmaxf(m_i[i], mx);
            alpha[i] = __expf(m_i[i] - m_new);
            m_i[i] = m_new;

            float2 cA = unpack2(s_con[i][0]);
            float2 cB = unpack2(s_con[i][1]);
            float2 oA = unpack2(s_off[i][0]);
            float2 oB = unpack2(s_off[i][1]);
            float cin[4] = {cA.x, cA.y, cB.x, cB.y};
            float oin[4] = {oA.x, oA.y, oB.x, oB.y};

            float lsum = 0.f, osum = 0.f;
#pragma unroll
            for (int j = 0; j < 4; j++) {
                float pw = __expf(lg[j] - m_new);
                float c = tanh_hw(cin[j] * INV_SQRT_H) * MAX_CONTRAST;
                float o = tanh_hw(oin[j] * INV_SQRT_H);
                lsum += pw;
                osum = fmaf(pw, o, osum);
                pc[i][j] = pw * c;
            }
            l_part[i]   = fmaf(l_part[i],   alpha[i], lsum);
            off_part[i] = fmaf(off_part[i], alpha[i], osum);
        }

        // Stage PC (transposed) and V tile
#pragma unroll
        for (int j = 0; j < 4; j++)
            *(float2*)&PCT[4 * tx + j][2 * ty] = make_float2(pc[0][j], pc[1][j]);
        {
            const int vc = tx * 4;
            const int vr = ty;
#pragma unroll
            for (int q = 0; q < 4; q++)
                *(float4*)&Vs[vr + 16 * q][vc] =
                    *(const float4*)&Vmat[(size_t)(d0 + vr + 16 * q) * OUTC + vc];
        }
        __syncthreads();

        // acc = acc*alpha + PC @ V
        {
            u64 al0 = pack2(alpha[0], alpha[0]);
            u64 al1 = pack2(alpha[1], alpha[1]);
            acc[0][0] = fmul2(acc[0][0], al0);
            acc[0][1] = fmul2(acc[0][1], al0);
            acc[1][0] = fmul2(acc[1][0], al1);
            acc[1][1] = fmul2(acc[1][1], al1);
        }
#pragma unroll 4
        for (int k = 0; k < 64; k++) {
            ulonglong2 v2 = *(const ulonglong2*)&Vs[k][4 * tx];
            float2 a2 = *(const float2*)&PCT[k][2 * ty];
            u64 a0 = pack2(a2.x, a2.x);
            u64 a1 = pack2(a2.y, a2.y);
            acc[0][0] = ffma2(a0, v2.x, acc[0][0]);
            acc[0][1] = ffma2(a0, v2.y, acc[0][1]);
            acc[1][0] = ffma2(a1, v2.x, acc[1][0]);
            acc[1][1] = ffma2(a1, v2.y, acc[1][1]);
        }
        // Next tile's chunk-loop syncs protect PCT/Vs reuse.
    }

    // Final epilogue: reduce l/off across the 16 tx-lanes, normalize, store.
#pragma unroll
    for (int i = 0; i < 2; i++) {
        float l = l_part[i], o = off_part[i];
#pragma unroll
        for (int d = 1; d < 16; d <<= 1) {
            l += __shfl_xor_sync(0xffffffffu, l, d);
            o += __shfl_xor_sync(0xffffffffu, o, d);
        }
        float inv = 1.0f / l;
        float2 a0 = unpack2(acc[i][0]);
        float2 a1 = unpack2(acc[i][1]);
        float4 o4 = make_float4((a0.x + o) * inv, (a0.y + o) * inv,
                                (a1.x + o) * inv, (a1.y + o) * inv);
        *(float4*)&out[(size_t)(r0 + 2 * ty + i) * OUTC + 4 * tx] = o4;
    }
}

// ---------------------------------------------------------------------------
extern "C" void kernel_launch(void* const* d_in, const int* in_sizes, int n_in,
                              void* d_out, int out_size)
{
    const float* pooled  = (const float*)d_in[0];
    const float* rlat    = (const float*)d_in[1];
    const float* dlat    = (const float*)d_in[2];
    const float* rpos    = (const float*)d_in[3];
    const float* dpos    = (const float*)d_in[4];
    const float* W_rproj = (const float*)d_in[5];
    const float* b_rproj = (const float*)d_in[6];
    const float* W_dproj = (const float*)d_in[7];
    const float* b_dproj = (const float*)d_in[8];
    const float* W_rcon  = (const float*)d_in[9];
    const float* b_rcon  = (const float*)d_in[10];
    const float* W_dcon  = (const float*)d_in[11];
    const float* b_dcon  = (const float*)d_in[12];
    const float* W_roff  = (const float*)d_in[13];
    const float* b_roff  = (const float*)d_in[14];
    const float* W_doff  = (const float*)d_in[15];
    const float* b_doff  = (const float*)d_in[16];
    float* out = (float*)d_out;

    dim3 blk(256);
    proj_kernel<<<dim3(8, NR / 64), blk>>>(rlat, rpos,
        W_rproj, b_rproj, W_rcon, b_rcon, W_roff, b_roff, 0);
    proj_kernel<<<dim3(8, ND / 64), blk>>>(dlat, dpos,
        W_dproj, b_dproj, W_dcon, b_dcon, W_doff, b_doff, 1);
    attn_kernel<<<NR / QROWS, blk>>>(pooled, out);
}